// round 1
// baseline (speedup 1.0000x reference)
#include <cuda_runtime.h>

// EnsKF step, restructured:
//   G  = E @ H                    (per batch, 256x8192 @ 8192x256)
//   Gc = G - colmean(G)           (center over ensemble)
//   A  = Gc^T Gc / ens + diag(std^2)        (SPD, 256x256)
//   innov[j,e] = ymean[j] - Gc[e,j] + noise[b,j,e]*std2[j]
//   Z  = A^{-1} innov             (Cholesky + blocked triangular solves)
//   M  = Gc @ Z / ens             (256x256)
//   Wp = I + M^T                  (mean-correction term vanishes: Gc cols sum to 0)
//   out = Wp @ E                  (per batch, 256x256 @ 256x8192)

#define BATCH 8
#define ENSN  256
#define XDIM  8192
#define YDIMN 256
#define NSQ   65536          // 256*256
#define SPLITS 16
#define KCH   512            // 8192 / SPLITS

__device__ float g_part[SPLITS * BATCH * NSQ];   // split-K partials for GEMM1
__device__ float g_G[BATCH * NSQ];               // G, then centered Gc  [b][e][j]
__device__ float g_A[BATCH * NSQ];               // A, then Cholesky L   [b][j][j']
__device__ float g_Z[BATCH * NSQ];               // innov, then Z        [b][j][e]
__device__ float g_W[BATCH * NSQ];               // Wp = I + M^T         [b][e][f]

// ---------------------------------------------------------------------------
// GEMM1 (split-K partials): g_part[s][b] += E[b, 128-tile, Kchunk] @ H[Kchunk, 128-tile]
// grid (4 tiles, SPLITS, BATCH), 256 threads, 128x128 tile, 8x8 micro
// ---------------------------------------------------------------------------
__global__ __launch_bounds__(256) void k_gemm1(const float* __restrict__ E,
                                               const float* __restrict__ H) {
    const int tm = blockIdx.x >> 1, tn = blockIdx.x & 1;
    const int s = blockIdx.y, b = blockIdx.z;
    const float* Ap = E + (size_t)b * ENSN * XDIM + (size_t)(tm * 128) * XDIM;
    const float* Bp = H + tn * 128;
    float* Cp = g_part + (size_t)(s * BATCH + b) * NSQ + (tm * 128) * 256 + tn * 128;

    __shared__ float As[16][128];
    __shared__ float Bs[16][128];

    const int tid = threadIdx.x;
    const int tx = tid & 15, ty = tid >> 4;
    const int lm = tid >> 1, lk = (tid & 1) * 8;      // A tile load: row, k-offset
    const int bk = tid >> 4, bn = (tid & 15) * 8;     // B tile load: k-row, col

    float acc[8][8];
#pragma unroll
    for (int i = 0; i < 8; i++)
#pragma unroll
        for (int j = 0; j < 8; j++) acc[i][j] = 0.0f;

    const int k0 = s * KCH;
    for (int kk = k0; kk < k0 + KCH; kk += 16) {
        float4 a0 = *(const float4*)(Ap + (size_t)lm * XDIM + kk + lk);
        float4 a1 = *(const float4*)(Ap + (size_t)lm * XDIM + kk + lk + 4);
        As[lk + 0][lm] = a0.x; As[lk + 1][lm] = a0.y;
        As[lk + 2][lm] = a0.z; As[lk + 3][lm] = a0.w;
        As[lk + 4][lm] = a1.x; As[lk + 5][lm] = a1.y;
        As[lk + 6][lm] = a1.z; As[lk + 7][lm] = a1.w;
        float4 b0 = *(const float4*)(Bp + (size_t)(kk + bk) * YDIMN + bn);
        float4 b1 = *(const float4*)(Bp + (size_t)(kk + bk) * YDIMN + bn + 4);
        *(float4*)&Bs[bk][bn] = b0;
        *(float4*)&Bs[bk][bn + 4] = b1;
        __syncthreads();
#pragma unroll
        for (int k = 0; k < 16; k++) {
            float4 av0 = *(float4*)&As[k][ty * 8];
            float4 av1 = *(float4*)&As[k][ty * 8 + 4];
            float4 bv0 = *(float4*)&Bs[k][tx * 8];
            float4 bv1 = *(float4*)&Bs[k][tx * 8 + 4];
            float a[8] = {av0.x, av0.y, av0.z, av0.w, av1.x, av1.y, av1.z, av1.w};
            float bb[8] = {bv0.x, bv0.y, bv0.z, bv0.w, bv1.x, bv1.y, bv1.z, bv1.w};
#pragma unroll
            for (int i = 0; i < 8; i++)
#pragma unroll
                for (int j = 0; j < 8; j++) acc[i][j] = fmaf(a[i], bb[j], acc[i][j]);
        }
        __syncthreads();
    }
#pragma unroll
    for (int i = 0; i < 8; i++)
#pragma unroll
        for (int j = 0; j < 8; j++)
            Cp[(ty * 8 + i) * 256 + tx * 8 + j] = acc[i][j];
}

// Deterministic split-K reduction: g_G = sum over splits of g_part
__global__ __launch_bounds__(256) void k_reduce() {
    const int i = blockIdx.x * 256 + threadIdx.x;    // over BATCH*NSQ = 524288
    float s = 0.0f;
#pragma unroll
    for (int p = 0; p < SPLITS; p++) s += g_part[(size_t)p * BATCH * NSQ + i];
    g_G[i] = s;
}

// ---------------------------------------------------------------------------
// Center G over ensemble (in place -> Gc) and build innov into g_Z [b][j][e]
// grid (BATCH), 256 threads (thread = column j)
// ---------------------------------------------------------------------------
__global__ __launch_bounds__(256) void k_center(const float* __restrict__ ymean,
                                                const float* __restrict__ ystd,
                                                const float* __restrict__ noise) {
    const int b = blockIdx.x, j = threadIdx.x;
    float* G = g_G + b * NSQ;
    float s = 0.0f;
    for (int e = 0; e < ENSN; e++) s += G[e * 256 + j];
    const float ym = s * (1.0f / 256.0f);
    const float ytm = ymean[j];
    const float sd = ystd[j];
    const float sd2 = sd * sd;
    const float* nz = noise + b * NSQ + j * 256;
    float* Zr = g_Z + b * NSQ + j * 256;
    for (int e = 0; e < ENSN; e++) {
        float gc = G[e * 256 + j] - ym;
        G[e * 256 + j] = gc;
        Zr[e] = ytm - gc + nz[e] * sd2;
    }
}

// ---------------------------------------------------------------------------
// A[u][v] = Gc^T Gc / ens + diag(std^2).  grid (16 tiles of 64x64, BATCH)
// ---------------------------------------------------------------------------
__global__ __launch_bounds__(256) void k_cyy(const float* __restrict__ ystd) {
    const int b = blockIdx.y;
    const int u0 = (blockIdx.x >> 2) * 64, v0 = (blockIdx.x & 3) * 64;
    const float* G = g_G + b * NSQ;
    float* A = g_A + b * NSQ;
    __shared__ float Us[16][64];
    __shared__ float Vs[16][64];
    const int tx = threadIdx.x & 15, ty = threadIdx.x >> 4;
    const int lk = threadIdx.x >> 4, lc = (threadIdx.x & 15) * 4;
    float acc[4][4];
#pragma unroll
    for (int i = 0; i < 4; i++)
#pragma unroll
        for (int j = 0; j < 4; j++) acc[i][j] = 0.0f;

    for (int ee = 0; ee < 256; ee += 16) {
        *(float4*)&Us[lk][lc] = *(const float4*)&G[(ee + lk) * 256 + u0 + lc];
        *(float4*)&Vs[lk][lc] = *(const float4*)&G[(ee + lk) * 256 + v0 + lc];
        __syncthreads();
#pragma unroll
        for (int k = 0; k < 16; k++) {
            float4 u = *(float4*)&Us[k][ty * 4];
            float4 v = *(float4*)&Vs[k][tx * 4];
            float ua[4] = {u.x, u.y, u.z, u.w};
            float va[4] = {v.x, v.y, v.z, v.w};
#pragma unroll
            for (int i = 0; i < 4; i++)
#pragma unroll
                for (int j = 0; j < 4; j++) acc[i][j] = fmaf(ua[i], va[j], acc[i][j]);
        }
        __syncthreads();
    }
#pragma unroll
    for (int i = 0; i < 4; i++)
#pragma unroll
        for (int j = 0; j < 4; j++) {
            const int u = u0 + ty * 4 + i, v = v0 + tx * 4 + j;
            float val = acc[i][j] * (1.0f / 256.0f);
            if (u == v) { float sd = ystd[u]; val += sd * sd; }
            A[u * 256 + v] = val;
        }
}

// ---------------------------------------------------------------------------
// Blocked Cholesky (panel 32, smem panel), one block per batch, in-place in g_A
// ---------------------------------------------------------------------------
__global__ __launch_bounds__(256) void k_chol() {
    const int b = blockIdx.x;
    float* a = g_A + b * NSQ;
    __shared__ float P[256][33];
    const int tid = threadIdx.x;

    for (int kb = 0; kb < 8; kb++) {
        const int j0 = kb * 32;
        if (tid >= j0) {
#pragma unroll
            for (int c = 0; c < 32; c++) P[tid][c] = a[tid * 256 + j0 + c];
        }
        __syncthreads();
        for (int k = 0; k < 32; k++) {
            const int gk = j0 + k;
            const float piv = P[gk][k];
            __syncthreads();                       // all reads of pivot done
            const float d = sqrtf(piv);
            const float rd = 1.0f / d;
            if (tid == gk) P[tid][k] = d;
            else if (tid > gk) P[tid][k] *= rd;
            __syncthreads();                       // column k scaled
            if (tid > gk) {
                const float lrk = P[tid][k];
#pragma unroll
                for (int c = k + 1; c < 32; c++) P[tid][c] -= lrk * P[j0 + c][k];
            }
            __syncthreads();                       // panel updated before next pivot
        }
        if (tid >= j0) {
#pragma unroll
            for (int c = 0; c < 32; c++) a[tid * 256 + j0 + c] = P[tid][c];
        }
        __syncthreads();
        const int rem = 224 - j0;                  // trailing rows/cols past panel
        if (rem > 0) {
            for (int idx = tid; idx < rem * rem; idx += 256) {
                const int r = j0 + 32 + idx / rem;
                const int c = j0 + 32 + (idx - (idx / rem) * rem);
                float acc = a[r * 256 + c];
#pragma unroll
                for (int k = 0; k < 32; k++) acc -= P[r][k] * P[c][k];
                a[r * 256 + c] = acc;
            }
        }
        __syncthreads();
    }
}

// ---------------------------------------------------------------------------
// Blocked triangular solves:  L y = innov, then L^T z = y  (in place in g_Z)
// grid (4 col-groups of 64 RHS, BATCH), 256 threads
// ---------------------------------------------------------------------------
__global__ __launch_bounds__(256) void k_trisolve() {
    const int b = blockIdx.y, g = blockIdx.x;
    const float* L = g_A + b * NSQ;
    float* Z = g_Z + b * NSQ;
    const int e0 = g * 64;

    __shared__ float D[32][33];
    __shared__ float X[32][64];
    __shared__ float Ls[224][33];
    const int tid = threadIdx.x;

    // ---- forward: L * Y = B ----
    for (int p = 0; p < 8; p++) {
        const int j0 = p * 32;
        {   // load diagonal block
            const int r = tid >> 3, cb = (tid & 7) * 4;
            float4 v = *(const float4*)&L[(j0 + r) * 256 + j0 + cb];
            D[r][cb] = v.x; D[r][cb + 1] = v.y; D[r][cb + 2] = v.z; D[r][cb + 3] = v.w;
        }
        const int rem = 224 - j0;
        for (int idx = tid; idx < rem * 32; idx += 256) {
            const int r = idx >> 5, c = idx & 31;
            Ls[r][c] = L[(j0 + 32 + r) * 256 + j0 + c];
        }
        __syncthreads();
        if (tid < 64) {
            const int c = e0 + tid;
            for (int k = 0; k < 32; k++) {
                float v = Z[(j0 + k) * 256 + c];
                for (int i = 0; i < k; i++) v -= D[k][i] * X[i][tid];
                v /= D[k][k];
                X[k][tid] = v;
                Z[(j0 + k) * 256 + c] = v;
            }
        }
        __syncthreads();
        for (int idx = tid; idx < rem * 64; idx += 256) {
            const int rr = idx >> 6, cc = idx & 63;
            float v = Z[(j0 + 32 + rr) * 256 + e0 + cc];
#pragma unroll
            for (int k = 0; k < 32; k++) v -= Ls[rr][k] * X[k][cc];
            Z[(j0 + 32 + rr) * 256 + e0 + cc] = v;
        }
        __syncthreads();
    }

    // ---- backward: L^T * Z = Y ----
    for (int p = 7; p >= 0; p--) {
        const int j0 = p * 32;
        {
            const int r = tid >> 3, cb = (tid & 7) * 4;
            float4 v = *(const float4*)&L[(j0 + r) * 256 + j0 + cb];
            D[r][cb] = v.x; D[r][cb + 1] = v.y; D[r][cb + 2] = v.z; D[r][cb + 3] = v.w;
        }
        for (int idx = tid; idx < j0 * 32; idx += 256) {     // Ls[r][k] = L[j0+k][r]
            const int r = idx >> 5, k = idx & 31;
            Ls[r][k] = L[(j0 + k) * 256 + r];
        }
        __syncthreads();
        if (tid < 64) {
            const int c = e0 + tid;
            for (int k = 31; k >= 0; k--) {
                float v = Z[(j0 + k) * 256 + c];
                for (int i = k + 1; i < 32; i++) v -= D[i][k] * X[i][tid];
                v /= D[k][k];
                X[k][tid] = v;
                Z[(j0 + k) * 256 + c] = v;
            }
        }
        __syncthreads();
        for (int idx = tid; idx < j0 * 64; idx += 256) {
            const int rr = idx >> 6, cc = idx & 63;
            float v = Z[rr * 256 + e0 + cc];
#pragma unroll
            for (int k = 0; k < 32; k++) v -= Ls[rr][k] * X[k][cc];
            Z[rr * 256 + e0 + cc] = v;
        }
        __syncthreads();
    }
}

// ---------------------------------------------------------------------------
// Wp[e][f] = (e==f) + (1/ens) * sum_j Gc[f][j] * Z[j][e]
// grid (16 tiles 64x64 over (e,f), BATCH)
// ---------------------------------------------------------------------------
__global__ __launch_bounds__(256) void k_wp() {
    const int b = blockIdx.y;
    const int e0 = (blockIdx.x >> 2) * 64, f0 = (blockIdx.x & 3) * 64;
    const float* G = g_G + b * NSQ;       // Gc
    const float* Z = g_Z + b * NSQ;
    float* W = g_W + b * NSQ;
    __shared__ float sZ[16][64];
    __shared__ float sG[16][64];
    const int tx = threadIdx.x & 15, ty = threadIdx.x >> 4;
    const int lk = threadIdx.x >> 4, lc = (threadIdx.x & 15) * 4;
    const int gn = threadIdx.x >> 2, gk = (threadIdx.x & 3) * 4;
    float acc[4][4];
#pragma unroll
    for (int i = 0; i < 4; i++)
#pragma unroll
        for (int j = 0; j < 4; j++) acc[i][j] = 0.0f;

    for (int jj = 0; jj < 256; jj += 16) {
        *(float4*)&sZ[lk][lc] = *(const float4*)&Z[(jj + lk) * 256 + e0 + lc];
        float4 gv = *(const float4*)&G[(f0 + gn) * 256 + jj + gk];
        sG[gk + 0][gn] = gv.x; sG[gk + 1][gn] = gv.y;
        sG[gk + 2][gn] = gv.z; sG[gk + 3][gn] = gv.w;
        __syncthreads();
#pragma unroll
        for (int k = 0; k < 16; k++) {
            float4 zv = *(float4*)&sZ[k][ty * 4];
            float4 gg = *(float4*)&sG[k][tx * 4];
            float za[4] = {zv.x, zv.y, zv.z, zv.w};
            float ga[4] = {gg.x, gg.y, gg.z, gg.w};
#pragma unroll
            for (int i = 0; i < 4; i++)
#pragma unroll
                for (int j = 0; j < 4; j++) acc[i][j] = fmaf(za[i], ga[j], acc[i][j]);
        }
        __syncthreads();
    }
#pragma unroll
    for (int i = 0; i < 4; i++)
#pragma unroll
        for (int j = 0; j < 4; j++) {
            const int e = e0 + ty * 4 + i, f = f0 + tx * 4 + j;
            float val = acc[i][j] * (1.0f / 256.0f);
            if (e == f) val += 1.0f;
            W[e * 256 + f] = val;
        }
}

// ---------------------------------------------------------------------------
// GEMM3: out[b] = Wp[b] @ E[b]   (M=256, N=8192, K=256)
// grid (64 n-tiles, 2 m-tiles, BATCH), 256 threads, 128x128 tile, 8x8 micro
// ---------------------------------------------------------------------------
__global__ __launch_bounds__(256) void k_gemm3(const float* __restrict__ E,
                                               float* __restrict__ out) {
    const int n0 = blockIdx.x * 128, m0 = blockIdx.y * 128, b = blockIdx.z;
    const float* Ap = g_W + b * NSQ + m0 * 256;
    const float* Bp = E + (size_t)b * ENSN * XDIM + n0;
    float* Cp = out + (size_t)b * ENSN * XDIM + (size_t)m0 * XDIM + n0;

    __shared__ float As[16][128];
    __shared__ float Bs[16][128];

    const int tid = threadIdx.x;
    const int tx = tid & 15, ty = tid >> 4;
    const int lm = tid >> 1, lk = (tid & 1) * 8;
    const int bk = tid >> 4, bn = (tid & 15) * 8;

    float acc[8][8];
#pragma unroll
    for (int i = 0; i < 8; i++)
#pragma unroll
        for (int j = 0; j < 8; j++) acc[i][j] = 0.0f;

    for (int kk = 0; kk < 256; kk += 16) {
        float4 a0 = *(const float4*)(Ap + lm * 256 + kk + lk);
        float4 a1 = *(const float4*)(Ap + lm * 256 + kk + lk + 4);
        As[lk + 0][lm] = a0.x; As[lk + 1][lm] = a0.y;
        As[lk + 2][lm] = a0.z; As[lk + 3][lm] = a0.w;
        As[lk + 4][lm] = a1.x; As[lk + 5][lm] = a1.y;
        As[lk + 6][lm] = a1.z; As[lk + 7][lm] = a1.w;
        float4 b0 = *(const float4*)(Bp + (size_t)(kk + bk) * XDIM + bn);
        float4 b1 = *(const float4*)(Bp + (size_t)(kk + bk) * XDIM + bn + 4);
        *(float4*)&Bs[bk][bn] = b0;
        *(float4*)&Bs[bk][bn + 4] = b1;
        __syncthreads();
#pragma unroll
        for (int k = 0; k < 16; k++) {
            float4 av0 = *(float4*)&As[k][ty * 8];
            float4 av1 = *(float4*)&As[k][ty * 8 + 4];
            float4 bv0 = *(float4*)&Bs[k][tx * 8];
            float4 bv1 = *(float4*)&Bs[k][tx * 8 + 4];
            float a[8] = {av0.x, av0.y, av0.z, av0.w, av1.x, av1.y, av1.z, av1.w};
            float bb[8] = {bv0.x, bv0.y, bv0.z, bv0.w, bv1.x, bv1.y, bv1.z, bv1.w};
#pragma unroll
            for (int i = 0; i < 8; i++)
#pragma unroll
                for (int j = 0; j < 8; j++) acc[i][j] = fmaf(a[i], bb[j], acc[i][j]);
        }
        __syncthreads();
    }
#pragma unroll
    for (int i = 0; i < 8; i++)
#pragma unroll
        for (int j = 0; j < 8; j++)
            Cp[(size_t)(ty * 8 + i) * XDIM + tx * 8 + j] = acc[i][j];
}

// ---------------------------------------------------------------------------
extern "C" void kernel_launch(void* const* d_in, const int* in_sizes, int n_in,
                              void* d_out, int out_size) {
    const float* E     = (const float*)d_in[0];   // [8, 256, 8192]
    const float* H     = (const float*)d_in[1];   // [8192, 256]
    const float* ymean = (const float*)d_in[2];   // [1, 256]
    const float* ystd  = (const float*)d_in[3];   // [1, 256]
    const float* noise = (const float*)d_in[4];   // [8, 256, 256]
    float* out = (float*)d_out;                   // [8, 256, 8192]

    k_gemm1<<<dim3(4, SPLITS, BATCH), 256>>>(E, H);
    k_reduce<<<(BATCH * NSQ) / 256, 256>>>();
    k_center<<<BATCH, 256>>>(ymean, ystd, noise);
    k_cyy<<<dim3(16, BATCH), 256>>>(ystd);
    k_chol<<<BATCH, 256>>>();
    k_trisolve<<<dim3(4, BATCH), 256>>>();
    k_wp<<<dim3(16, BATCH), 256>>>();
    k_gemm3<<<dim3(64, 2, BATCH), 256>>>(E, out);
}

// round 2
// speedup vs baseline: 1.2376x; 1.2376x over previous
#include <cuda_runtime.h>
#include <cstdint>

// EnsKF step, restructured:
//   G  = E @ H                         (tf32x3 tensor GEMM, split-K)
//   Gc = G - colmean(G);  innov built transposed
//   A  = Gc^T Gc / ens + diag(std^2)   (SPD)
//   Z  = A^{-1} innov                  (Cholesky + blocked triangular solves)
//   Wp = I + (Gc @ Z / ens)^T
//   out = Wp @ E                       (tf32x3 tensor GEMM)

#define BATCH 8
#define ENSN  256
#define XDIM  8192
#define NSQ   65536
#define SPLITS 8
#define KCH   1024

__device__ float g_part[SPLITS * BATCH * NSQ];
__device__ float g_G[BATCH * NSQ];     // G then Gc   [b][e][j]
__device__ float g_mu[BATCH * 256];
__device__ float g_A[BATCH * NSQ];     // A then L
__device__ float g_Z[BATCH * NSQ];     // innov then Z [b][j][e]
__device__ float g_W[BATCH * NSQ];     // Wp          [b][e][f]

// ---------------------------------------------------------------------------
// tf32 helpers
// ---------------------------------------------------------------------------
__device__ __forceinline__ uint32_t f2tf(float x) {
    uint32_t r;
    asm("cvt.rna.tf32.f32 %0, %1;" : "=r"(r) : "f"(x));
    return r;
}

__device__ __forceinline__ void mma8(float* c,
                                     uint32_t a0, uint32_t a1, uint32_t a2, uint32_t a3,
                                     uint32_t b0, uint32_t b1) {
    asm volatile(
        "mma.sync.aligned.m16n8k8.row.col.f32.tf32.tf32.f32 "
        "{%0,%1,%2,%3}, {%4,%5,%6,%7}, {%8,%9}, {%0,%1,%2,%3};"
        : "+f"(c[0]), "+f"(c[1]), "+f"(c[2]), "+f"(c[3])
        : "r"(a0), "r"(a1), "r"(a2), "r"(a3), "r"(b0), "r"(b1));
}

// ---------------------------------------------------------------------------
// Shared 128x128xK tf32x3 GEMM body. A: [128 x K] row-major stride lda.
// B: [K x 128] row-major stride ldb. C: [128 x 128] stride ldc.
// 256 threads, 8 warps in 4(m) x 2(n), warp tile 32x64.
// ---------------------------------------------------------------------------
__device__ __forceinline__ void gemm128_tf32x3(
    const float* __restrict__ Ag, size_t lda,
    const float* __restrict__ Bg, size_t ldb,
    float* __restrict__ Cg, size_t ldc, int kiters)
{
    __shared__ float As[32][136];   // [k][m], stride 136 -> conflict-free frags
    __shared__ float Bs[32][136];   // [k][n]

    const int tid = threadIdx.x;
    const int lane = tid & 31, w = tid >> 5;
    const int wm = (w & 3) * 32, wn = (w >> 2) * 64;
    const int g = lane >> 2, tig = lane & 3;

    const int ar = tid >> 1, ak = (tid & 1) * 16;    // A tile: row, k-base
    const int bk = tid >> 3, bn = (tid & 7) * 16;    // B tile: k-row, n-base

    float c[2][8][4];
#pragma unroll
    for (int i = 0; i < 2; i++)
#pragma unroll
        for (int j = 0; j < 8; j++)
#pragma unroll
            for (int q = 0; q < 4; q++) c[i][j][q] = 0.0f;

    float4 pa[4], pb[4];
#pragma unroll
    for (int i = 0; i < 4; i++) pa[i] = *(const float4*)(Ag + (size_t)ar * lda + ak + i * 4);
#pragma unroll
    for (int i = 0; i < 4; i++) pb[i] = *(const float4*)(Bg + (size_t)bk * ldb + bn + i * 4);

    for (int it = 0; it < kiters; it++) {
#pragma unroll
        for (int i = 0; i < 4; i++) {
            As[ak + i * 4 + 0][ar] = pa[i].x;
            As[ak + i * 4 + 1][ar] = pa[i].y;
            As[ak + i * 4 + 2][ar] = pa[i].z;
            As[ak + i * 4 + 3][ar] = pa[i].w;
            *(float4*)&Bs[bk][bn + i * 4] = pb[i];
        }
        __syncthreads();
        if (it + 1 < kiters) {
            const float* An = Ag + (size_t)(it + 1) * 32;
            const float* Bn = Bg + (size_t)(it + 1) * 32 * ldb;
#pragma unroll
            for (int i = 0; i < 4; i++) pa[i] = *(const float4*)(An + (size_t)ar * lda + ak + i * 4);
#pragma unroll
            for (int i = 0; i < 4; i++) pb[i] = *(const float4*)(Bn + (size_t)bk * ldb + bn + i * 4);
        }
#pragma unroll
        for (int k8 = 0; k8 < 4; k8++) {
            const int kb = k8 * 8;
            uint32_t bhi[8][2], blo[8][2];
#pragma unroll
            for (int nt = 0; nt < 8; nt++) {
                float b0 = Bs[kb + tig][wn + nt * 8 + g];
                float b1 = Bs[kb + tig + 4][wn + nt * 8 + g];
                bhi[nt][0] = f2tf(b0);
                blo[nt][0] = f2tf(b0 - __uint_as_float(bhi[nt][0]));
                bhi[nt][1] = f2tf(b1);
                blo[nt][1] = f2tf(b1 - __uint_as_float(bhi[nt][1]));
            }
#pragma unroll
            for (int mt = 0; mt < 2; mt++) {
                float a0 = As[kb + tig][wm + mt * 16 + g];
                float a1 = As[kb + tig][wm + mt * 16 + g + 8];
                float a2 = As[kb + tig + 4][wm + mt * 16 + g];
                float a3 = As[kb + tig + 4][wm + mt * 16 + g + 8];
                uint32_t ah0 = f2tf(a0), ah1 = f2tf(a1), ah2 = f2tf(a2), ah3 = f2tf(a3);
                uint32_t al0 = f2tf(a0 - __uint_as_float(ah0));
                uint32_t al1 = f2tf(a1 - __uint_as_float(ah1));
                uint32_t al2 = f2tf(a2 - __uint_as_float(ah2));
                uint32_t al3 = f2tf(a3 - __uint_as_float(ah3));
#pragma unroll
                for (int nt = 0; nt < 8; nt++)
                    mma8(c[mt][nt], al0, al1, al2, al3, bhi[nt][0], bhi[nt][1]);
#pragma unroll
                for (int nt = 0; nt < 8; nt++)
                    mma8(c[mt][nt], ah0, ah1, ah2, ah3, blo[nt][0], blo[nt][1]);
#pragma unroll
                for (int nt = 0; nt < 8; nt++)
                    mma8(c[mt][nt], ah0, ah1, ah2, ah3, bhi[nt][0], bhi[nt][1]);
            }
        }
        __syncthreads();
    }
#pragma unroll
    for (int mt = 0; mt < 2; mt++)
#pragma unroll
        for (int nt = 0; nt < 8; nt++) {
            const int row = wm + mt * 16 + g;
            const int col = wn + nt * 8 + tig * 2;
            *(float2*)(Cg + (size_t)row * ldc + col) = make_float2(c[mt][nt][0], c[mt][nt][1]);
            *(float2*)(Cg + (size_t)(row + 8) * ldc + col) = make_float2(c[mt][nt][2], c[mt][nt][3]);
        }
}

// ---------------------------------------------------------------------------
// GEMM1: split-K partials of G = E @ H
// ---------------------------------------------------------------------------
__global__ __launch_bounds__(256, 1) void k_gemm1(const float* __restrict__ E,
                                                  const float* __restrict__ H) {
    const int tm = blockIdx.x >> 1, tn = blockIdx.x & 1;
    const int s = blockIdx.y, b = blockIdx.z;
    const float* Ag = E + (size_t)b * ENSN * XDIM + (size_t)(tm * 128) * XDIM + (size_t)s * KCH;
    const float* Bg = H + (size_t)(s * KCH) * 256 + tn * 128;
    float* Cg = g_part + (size_t)(s * BATCH + b) * NSQ + (tm * 128) * 256 + tn * 128;
    gemm128_tf32x3(Ag, XDIM, Bg, 256, Cg, 256, KCH / 32);
}

// Deterministic split-K reduction (float4)
__global__ __launch_bounds__(256) void k_reduce() {
    const int i = blockIdx.x * 256 + threadIdx.x;          // 0..131071
    const float4* P = (const float4*)g_part;
    float4 s = P[i];
#pragma unroll
    for (int p = 1; p < SPLITS; p++) {
        float4 v = P[(size_t)p * (BATCH * NSQ / 4) + i];
        s.x += v.x; s.y += v.y; s.z += v.z; s.w += v.w;
    }
    ((float4*)g_G)[i] = s;
}

// ---------------------------------------------------------------------------
// Column means of G over ensemble. grid (8 j-blocks, 8 batch)
// ---------------------------------------------------------------------------
__global__ __launch_bounds__(256) void k_colmean() {
    const int b = blockIdx.y;
    const int j = blockIdx.x * 32 + (threadIdx.x & 31);
    const int er = threadIdx.x >> 5;
    const float* G = g_G + b * NSQ;
    float s = 0.0f;
    for (int e = er; e < ENSN; e += 8) s += G[e * 256 + j];
    __shared__ float red[8][32];
    red[er][threadIdx.x & 31] = s;
    __syncthreads();
    if (er == 0) {
        float t = 0.0f;
#pragma unroll
        for (int r = 0; r < 8; r++) t += red[r][threadIdx.x & 31];
        g_mu[b * 256 + j] = t * (1.0f / 256.0f);
    }
}

// ---------------------------------------------------------------------------
// Center G in place and build innov (transposed) via smem transpose.
// grid (8 e-tiles, 8 j-tiles, 8 batch), 256 threads
// ---------------------------------------------------------------------------
__global__ __launch_bounds__(256) void k_centerT(const float* __restrict__ ymean,
                                                 const float* __restrict__ ystd,
                                                 const float* __restrict__ noise) {
    const int b = blockIdx.z, j0 = blockIdx.y * 32, e0 = blockIdx.x * 32;
    float* G = g_G + b * NSQ;
    float* Z = g_Z + b * NSQ;
    const float* nz = noise + b * NSQ;
    __shared__ float T[32][33];
    const int tx = threadIdx.x & 31, ty = threadIdx.x >> 5;
    const float mu = g_mu[b * 256 + j0 + tx];
#pragma unroll
    for (int r = 0; r < 4; r++) {
        const int e = e0 + ty + r * 8;
        float gc = G[e * 256 + j0 + tx] - mu;
        G[e * 256 + j0 + tx] = gc;
        T[ty + r * 8][tx] = gc;
    }
    __syncthreads();
#pragma unroll
    for (int r = 0; r < 4; r++) {
        const int j = j0 + ty + r * 8;
        const float ym = ymean[j];
        const float sd = ystd[j];
        const float sd2 = sd * sd;
        const int e = e0 + tx;
        Z[j * 256 + e] = ym - T[tx][ty + r * 8] + nz[j * 256 + e] * sd2;
    }
}

// ---------------------------------------------------------------------------
// A[u][v] = Gc^T Gc / ens + diag(std^2).  grid (16 tiles of 64x64, BATCH)
// ---------------------------------------------------------------------------
__global__ __launch_bounds__(256) void k_cyy(const float* __restrict__ ystd) {
    const int b = blockIdx.y;
    const int u0 = (blockIdx.x >> 2) * 64, v0 = (blockIdx.x & 3) * 64;
    const float* G = g_G + b * NSQ;
    float* A = g_A + b * NSQ;
    __shared__ float Us[16][64];
    __shared__ float Vs[16][64];
    const int tx = threadIdx.x & 15, ty = threadIdx.x >> 4;
    const int lk = threadIdx.x >> 4, lc = (threadIdx.x & 15) * 4;
    float acc[4][4];
#pragma unroll
    for (int i = 0; i < 4; i++)
#pragma unroll
        for (int j = 0; j < 4; j++) acc[i][j] = 0.0f;

    for (int ee = 0; ee < 256; ee += 16) {
        *(float4*)&Us[lk][lc] = *(const float4*)&G[(ee + lk) * 256 + u0 + lc];
        *(float4*)&Vs[lk][lc] = *(const float4*)&G[(ee + lk) * 256 + v0 + lc];
        __syncthreads();
#pragma unroll
        for (int k = 0; k < 16; k++) {
            float4 u = *(float4*)&Us[k][ty * 4];
            float4 v = *(float4*)&Vs[k][tx * 4];
            float ua[4] = {u.x, u.y, u.z, u.w};
            float va[4] = {v.x, v.y, v.z, v.w};
#pragma unroll
            for (int i = 0; i < 4; i++)
#pragma unroll
                for (int j = 0; j < 4; j++) acc[i][j] = fmaf(ua[i], va[j], acc[i][j]);
        }
        __syncthreads();
    }
#pragma unroll
    for (int i = 0; i < 4; i++)
#pragma unroll
        for (int j = 0; j < 4; j++) {
            const int u = u0 + ty * 4 + i, v = v0 + tx * 4 + j;
            float val = acc[i][j] * (1.0f / 256.0f);
            if (u == v) { float sd = ystd[u]; val += sd * sd; }
            A[u * 256 + v] = val;
        }
}

// ---------------------------------------------------------------------------
// Blocked Cholesky (panel 32), one block per batch
// ---------------------------------------------------------------------------
__global__ __launch_bounds__(256) void k_chol() {
    const int b = blockIdx.x;
    float* a = g_A + b * NSQ;
    __shared__ float P[256][33];
    const int tid = threadIdx.x;

    for (int kb = 0; kb < 8; kb++) {
        const int j0 = kb * 32;
        if (tid >= j0) {
#pragma unroll
            for (int c = 0; c < 32; c++) P[tid][c] = a[tid * 256 + j0 + c];
        }
        __syncthreads();
        for (int k = 0; k < 32; k++) {
            const int gk = j0 + k;
            const float piv = P[gk][k];
            __syncthreads();
            const float d = sqrtf(piv);
            const float rd = 1.0f / d;
            if (tid == gk) P[tid][k] = d;
            else if (tid > gk) P[tid][k] *= rd;
            __syncthreads();
            if (tid > gk) {
                const float lrk = P[tid][k];
#pragma unroll
                for (int c = k + 1; c < 32; c++) P[tid][c] -= lrk * P[j0 + c][k];
            }
            __syncthreads();
        }
        if (tid >= j0) {
#pragma unroll
            for (int c = 0; c < 32; c++) a[tid * 256 + j0 + c] = P[tid][c];
        }
        __syncthreads();
        const int rem = 224 - j0;
        if (rem > 0) {
            for (int idx = tid; idx < rem * rem; idx += 256) {
                const int r = j0 + 32 + idx / rem;
                const int c = j0 + 32 + (idx - (idx / rem) * rem);
                float acc = a[r * 256 + c];
#pragma unroll
                for (int k = 0; k < 32; k++) acc -= P[r][k] * P[c][k];
                a[r * 256 + c] = acc;
            }
        }
        __syncthreads();
    }
}

// ---------------------------------------------------------------------------
// Blocked triangular solves:  L y = innov, then L^T z = y  (in place in g_Z)
// grid (4 col-groups of 64 RHS, BATCH), 256 threads
// ---------------------------------------------------------------------------
__global__ __launch_bounds__(256) void k_trisolve() {
    const int b = blockIdx.y, grp = blockIdx.x;
    const float* L = g_A + b * NSQ;
    float* Z = g_Z + b * NSQ;
    const int e0 = grp * 64;

    __shared__ float D[32][33];
    __shared__ float X[32][64];
    __shared__ float Ls[224][33];
    const int tid = threadIdx.x;

    for (int p = 0; p < 8; p++) {
        const int j0 = p * 32;
        {
            const int r = tid >> 3, cb = (tid & 7) * 4;
            float4 v = *(const float4*)&L[(j0 + r) * 256 + j0 + cb];
            D[r][cb] = v.x; D[r][cb + 1] = v.y; D[r][cb + 2] = v.z; D[r][cb + 3] = v.w;
        }
        const int rem = 224 - j0;
        for (int idx = tid; idx < rem * 32; idx += 256) {
            const int r = idx >> 5, c = idx & 31;
            Ls[r][c] = L[(j0 + 32 + r) * 256 + j0 + c];
        }
        __syncthreads();
        if (tid < 64) {
            const int c = e0 + tid;
            for (int k = 0; k < 32; k++) {
                float v = Z[(j0 + k) * 256 + c];
                for (int i = 0; i < k; i++) v -= D[k][i] * X[i][tid];
                v /= D[k][k];
                X[k][tid] = v;
                Z[(j0 + k) * 256 + c] = v;
            }
        }
        __syncthreads();
        for (int idx = tid; idx < rem * 64; idx += 256) {
            const int rr = idx >> 6, cc = idx & 63;
            float v = Z[(j0 + 32 + rr) * 256 + e0 + cc];
#pragma unroll
            for (int k = 0; k < 32; k++) v -= Ls[rr][k] * X[k][cc];
            Z[(j0 + 32 + rr) * 256 + e0 + cc] = v;
        }
        __syncthreads();
    }

    for (int p = 7; p >= 0; p--) {
        const int j0 = p * 32;
        {
            const int r = tid >> 3, cb = (tid & 7) * 4;
            float4 v = *(const float4*)&L[(j0 + r) * 256 + j0 + cb];
            D[r][cb] = v.x; D[r][cb + 1] = v.y; D[r][cb + 2] = v.z; D[r][cb + 3] = v.w;
        }
        for (int idx = tid; idx < j0 * 32; idx += 256) {
            const int r = idx >> 5, k = idx & 31;
            Ls[r][k] = L[(j0 + k) * 256 + r];
        }
        __syncthreads();
        if (tid < 64) {
            const int c = e0 + tid;
            for (int k = 31; k >= 0; k--) {
                float v = Z[(j0 + k) * 256 + c];
                for (int i = k + 1; i < 32; i++) v -= D[i][k] * X[i][tid];
                v /= D[k][k];
                X[k][tid] = v;
                Z[(j0 + k) * 256 + c] = v;
            }
        }
        __syncthreads();
        for (int idx = tid; idx < j0 * 64; idx += 256) {
            const int rr = idx >> 6, cc = idx & 63;
            float v = Z[rr * 256 + e0 + cc];
#pragma unroll
            for (int k = 0; k < 32; k++) v -= Ls[rr][k] * X[k][cc];
            Z[rr * 256 + e0 + cc] = v;
        }
        __syncthreads();
    }
}

// ---------------------------------------------------------------------------
// Wp[e][f] = (e==f) + (1/ens) * sum_j Gc[f][j] * Z[j][e]
// ---------------------------------------------------------------------------
__global__ __launch_bounds__(256) void k_wp() {
    const int b = blockIdx.y;
    const int e0 = (blockIdx.x >> 2) * 64, f0 = (blockIdx.x & 3) * 64;
    const float* G = g_G + b * NSQ;
    const float* Z = g_Z + b * NSQ;
    float* W = g_W + b * NSQ;
    __shared__ float sZ[16][64];
    __shared__ float sG[16][64];
    const int tx = threadIdx.x & 15, ty = threadIdx.x >> 4;
    const int lk = threadIdx.x >> 4, lc = (threadIdx.x & 15) * 4;
    const int gn = threadIdx.x >> 2, gk = (threadIdx.x & 3) * 4;
    float acc[4][4];
#pragma unroll
    for (int i = 0; i < 4; i++)
#pragma unroll
        for (int j = 0; j < 4; j++) acc[i][j] = 0.0f;

    for (int jj = 0; jj < 256; jj += 16) {
        *(float4*)&sZ[lk][lc] = *(const float4*)&Z[(jj + lk) * 256 + e0 + lc];
        float4 gv = *(const float4*)&G[(f0 + gn) * 256 + jj + gk];
        sG[gk + 0][gn] = gv.x; sG[gk + 1][gn] = gv.y;
        sG[gk + 2][gn] = gv.z; sG[gk + 3][gn] = gv.w;
        __syncthreads();
#pragma unroll
        for (int k = 0; k < 16; k++) {
            float4 zv = *(float4*)&sZ[k][ty * 4];
            float4 gg = *(float4*)&sG[k][tx * 4];
            float za[4] = {zv.x, zv.y, zv.z, zv.w};
            float ga[4] = {gg.x, gg.y, gg.z, gg.w};
#pragma unroll
            for (int i = 0; i < 4; i++)
#pragma unroll
                for (int j = 0; j < 4; j++) acc[i][j] = fmaf(za[i], ga[j], acc[i][j]);
        }
        __syncthreads();
    }
#pragma unroll
    for (int i = 0; i < 4; i++)
#pragma unroll
        for (int j = 0; j < 4; j++) {
            const int e = e0 + ty * 4 + i, f = f0 + tx * 4 + j;
            float val = acc[i][j] * (1.0f / 256.0f);
            if (e == f) val += 1.0f;
            W[e * 256 + f] = val;
        }
}

// ---------------------------------------------------------------------------
// GEMM3: out[b] = Wp[b] @ E[b]
// ---------------------------------------------------------------------------
__global__ __launch_bounds__(256, 1) void k_gemm3(const float* __restrict__ E,
                                                  float* __restrict__ out) {
    const int n0 = blockIdx.x * 128, m0 = blockIdx.y * 128, b = blockIdx.z;
    const float* Ag = g_W + (size_t)b * NSQ + m0 * 256;
    const float* Bg = E + (size_t)b * ENSN * XDIM + n0;
    float* Cg = out + (size_t)b * ENSN * XDIM + (size_t)m0 * XDIM + n0;
    gemm128_tf32x3(Ag, 256, Bg, XDIM, Cg, XDIM, 256 / 32);
}

// ---------------------------------------------------------------------------
extern "C" void kernel_launch(void* const* d_in, const int* in_sizes, int n_in,
                              void* d_out, int out_size) {
    const float* E     = (const float*)d_in[0];   // [8, 256, 8192]
    const float* H     = (const float*)d_in[1];   // [8192, 256]
    const float* ymean = (const float*)d_in[2];   // [1, 256]
    const float* ystd  = (const float*)d_in[3];   // [1, 256]
    const float* noise = (const float*)d_in[4];   // [8, 256, 256]
    float* out = (float*)d_out;                   // [8, 256, 8192]

    k_gemm1<<<dim3(4, SPLITS, BATCH), 256>>>(E, H);
    k_reduce<<<(BATCH * NSQ / 4) / 256, 256>>>();
    k_colmean<<<dim3(8, BATCH), 256>>>();
    k_centerT<<<dim3(8, 8, BATCH), 256>>>(ymean, ystd, noise);
    k_cyy<<<dim3(16, BATCH), 256>>>(ystd);
    k_chol<<<BATCH, 256>>>();
    k_trisolve<<<dim3(4, BATCH), 256>>>();
    k_wp<<<dim3(16, BATCH), 256>>>();
    k_gemm3<<<dim3(64, 2, BATCH), 256>>>(E, out);
}

// round 4
// speedup vs baseline: 1.4342x; 1.1588x over previous
#include <cuda_runtime.h>
#include <cuda_bf16.h>
#include <cstdint>

// EnsKF step. Legacy tensor path (compute_103 portable ISA):
//   splits: Ehi/Elo [b][e][x], Hhi/Hlo [x][j]  (bf16 hi/lo, no transposes)
//   G  = E @ H          (mma.m16n8k16.bf16, 4-term split, split-K)
//   Gc = G - colmean;  A = Gc^T Gc/ens + diag(std^2);  Z = A^{-1} innov
//   Mt[e][f] = (1/ens) sum_j Z[j][e] Gc[f][j]  -> bf16 hi/lo
//   out = E + Mt @ E    (mma bf16 4-term, epilogue adds E)

#define BATCH 8
#define ENSN  256
#define XDIM  8192
#define NSQ   65536
#define SPLITS 8

__device__ __align__(256) float g_part[SPLITS * BATCH * NSQ];
__device__ __align__(256) float g_G[BATCH * NSQ];
__device__ __align__(256) float g_mu[BATCH * 256];
__device__ __align__(256) float g_A[BATCH * NSQ];
__device__ __align__(256) float g_Z[BATCH * NSQ];
__device__ __align__(256) __nv_bfloat16 g_Ehi[BATCH * ENSN * XDIM];
__device__ __align__(256) __nv_bfloat16 g_Elo[BATCH * ENSN * XDIM];
__device__ __align__(256) __nv_bfloat16 g_Hhi[XDIM * 256];
__device__ __align__(256) __nv_bfloat16 g_Hlo[XDIM * 256];
__device__ __align__(256) __nv_bfloat16 g_Whi[BATCH * NSQ];
__device__ __align__(256) __nv_bfloat16 g_Wlo[BATCH * NSQ];

// ---------------- smem layout (bytes) ----------------
// A: [buf][hl][128 rows][40 el] bf16 -> tile 10240, hl stride 10240, buf 20480
// B: [buf][hl][32 rows][136 el] bf16 -> tile 8704,  hl stride 8704,  buf 17408
#define SM_A(buf, hl) ((buf) * 20480 + (hl) * 10240)
#define SM_B(buf, hl) (40960 + (buf) * 17408 + (hl) * 8704)
#define SMEMSZ (40960 + 34816)

// ---------------- low-level helpers ----------------
__device__ __forceinline__ uint32_t smem_u32(const void* p) {
    uint32_t a;
    asm("{ .reg .u64 t; cvta.to.shared.u64 t, %1; cvt.u32.u64 %0, t; }" : "=r"(a) : "l"(p));
    return a;
}
__device__ __forceinline__ void cpa16(uint32_t dst, const void* src) {
    asm volatile("cp.async.cg.shared.global [%0], [%1], 16;" :: "r"(dst), "l"(src));
}
__device__ __forceinline__ void ldsm4(uint32_t* r, uint32_t a) {
    asm volatile("ldmatrix.sync.aligned.m8n8.x4.shared.b16 {%0,%1,%2,%3}, [%4];"
                 : "=r"(r[0]), "=r"(r[1]), "=r"(r[2]), "=r"(r[3]) : "r"(a));
}
__device__ __forceinline__ void ldsm4t(uint32_t* r, uint32_t a) {
    asm volatile("ldmatrix.sync.aligned.m8n8.x4.trans.shared.b16 {%0,%1,%2,%3}, [%4];"
                 : "=r"(r[0]), "=r"(r[1]), "=r"(r[2]), "=r"(r[3]) : "r"(a));
}
__device__ __forceinline__ void mma16816(float* c, const uint32_t* a, const uint32_t* b) {
    asm volatile("mma.sync.aligned.m16n8k16.row.col.f32.bf16.bf16.f32 "
                 "{%0,%1,%2,%3},{%4,%5,%6,%7},{%8,%9},{%0,%1,%2,%3};"
                 : "+f"(c[0]), "+f"(c[1]), "+f"(c[2]), "+f"(c[3])
                 : "r"(a[0]), "r"(a[1]), "r"(a[2]), "r"(a[3]), "r"(b[0]), "r"(b[1]));
}

// ---------------- tile producers ----------------
__device__ __forceinline__ void issue_tiles(
    uint32_t sb, int buf,
    const __nv_bfloat16* __restrict__ Ahi, const __nv_bfloat16* __restrict__ Alo, size_t lda,
    const __nv_bfloat16* __restrict__ Bhi, const __nv_bfloat16* __restrict__ Blo, size_t ldb,
    int kbase, int tid)
{
#pragma unroll
    for (int half = 0; half < 2; half++) {
        const __nv_bfloat16* src = half ? Alo : Ahi;
#pragma unroll
        for (int it = 0; it < 2; it++) {
            const int i = tid + it * 256;             // 512 transfers: [128 rows][4 segs]
            const int r = i >> 2, seg = i & 3;
            cpa16(sb + SM_A(buf, half) + r * 80 + seg * 16,
                  src + (size_t)r * lda + kbase + seg * 8);
        }
    }
#pragma unroll
    for (int half = 0; half < 2; half++) {
        const __nv_bfloat16* src = half ? Blo : Bhi;
#pragma unroll
        for (int it = 0; it < 2; it++) {
            const int i = tid + it * 256;             // 512 transfers: [32 rows][16 segs]
            const int r = i >> 4, seg = i & 15;
            cpa16(sb + SM_B(buf, half) + r * 272 + seg * 16,
                  src + (size_t)(kbase + r) * ldb + seg * 8);
        }
    }
}

// ---------------- warp compute: one 32-K chunk, 4-term bf16 split ----------------
__device__ __forceinline__ void compute_chunk(uint32_t sb, int buf, int lane,
                                              int wm, int wn, float acc[4][4][4]) {
    const int arow = lane & 15, aoff = (lane >> 4) * 16;
    const int brow = (lane & 7) + ((lane >> 3) & 1) * 8, boff = (lane >> 4) * 16;
#pragma unroll
    for (int k16 = 0; k16 < 2; k16++) {
        uint32_t ah[4][4], al[4][4], bh[2][4], bl[2][4];
#pragma unroll
        for (int mi = 0; mi < 4; mi++)
            ldsm4(ah[mi], sb + SM_A(buf, 0) + (wm + 16 * mi + arow) * 80 + k16 * 32 + aoff);
#pragma unroll
        for (int nj = 0; nj < 2; nj++)
            ldsm4t(bh[nj], sb + SM_B(buf, 0) + (k16 * 16 + brow) * 272 + (wn + nj * 16) * 2 + boff);
#pragma unroll
        for (int mi = 0; mi < 4; mi++)
#pragma unroll
            for (int n8 = 0; n8 < 4; n8++)
                mma16816(acc[mi][n8], ah[mi], &bh[n8 >> 1][(n8 & 1) * 2]);
#pragma unroll
        for (int nj = 0; nj < 2; nj++)
            ldsm4t(bl[nj], sb + SM_B(buf, 1) + (k16 * 16 + brow) * 272 + (wn + nj * 16) * 2 + boff);
#pragma unroll
        for (int mi = 0; mi < 4; mi++)
#pragma unroll
            for (int n8 = 0; n8 < 4; n8++)
                mma16816(acc[mi][n8], ah[mi], &bl[n8 >> 1][(n8 & 1) * 2]);
#pragma unroll
        for (int mi = 0; mi < 4; mi++)
            ldsm4(al[mi], sb + SM_A(buf, 1) + (wm + 16 * mi + arow) * 80 + k16 * 32 + aoff);
#pragma unroll
        for (int mi = 0; mi < 4; mi++)
#pragma unroll
            for (int n8 = 0; n8 < 4; n8++)
                mma16816(acc[mi][n8], al[mi], &bh[n8 >> 1][(n8 & 1) * 2]);
#pragma unroll
        for (int mi = 0; mi < 4; mi++)
#pragma unroll
            for (int n8 = 0; n8 < 4; n8++)
                mma16816(acc[mi][n8], al[mi], &bl[n8 >> 1][(n8 & 1) * 2]);
    }
}

// ---------------- main accumulate driver (128m x 128n CTA) ----------------
__device__ __forceinline__ void mm_main(
    const __nv_bfloat16* Ahi, const __nv_bfloat16* Alo, size_t lda,
    const __nv_bfloat16* Bhi, const __nv_bfloat16* Blo, size_t ldb,
    int nch, float acc[4][4][4], char* smem)
{
    const uint32_t sb = smem_u32(smem);
    const int tid = threadIdx.x, lane = tid & 31, w = tid >> 5;
    const int wm = (w & 1) * 64, wn = (w >> 1) * 32;
#pragma unroll
    for (int i = 0; i < 4; i++)
#pragma unroll
        for (int j = 0; j < 4; j++)
#pragma unroll
            for (int q = 0; q < 4; q++) acc[i][j][q] = 0.0f;

    issue_tiles(sb, 0, Ahi, Alo, lda, Bhi, Blo, ldb, 0, tid);
    asm volatile("cp.async.commit_group;" ::: "memory");
    issue_tiles(sb, 1, Ahi, Alo, lda, Bhi, Blo, ldb, 32, tid);
    asm volatile("cp.async.commit_group;" ::: "memory");

    for (int c = 0; c < nch; c++) {
        asm volatile("cp.async.wait_group 1;" ::: "memory");
        __syncthreads();
        compute_chunk(sb, c & 1, lane, wm, wn, acc);
        __syncthreads();
        if (c + 2 < nch)
            issue_tiles(sb, c & 1, Ahi, Alo, lda, Bhi, Blo, ldb, (c + 2) * 32, tid);
        asm volatile("cp.async.commit_group;" ::: "memory");
    }
}

// ---------------------------------------------------------------------------
// GEMM1: split-K partials of G = E @ H.  grid(4 = mt*2+nt, 8 splits, 8 b)
// ---------------------------------------------------------------------------
__global__ __launch_bounds__(256, 1) void k_mm1() {
    extern __shared__ char smem[];
    const int mt = blockIdx.x >> 1, nt = blockIdx.x & 1;
    const int s = blockIdx.y, b = blockIdx.z;
    const size_t aoff = ((size_t)b * ENSN + mt * 128) * XDIM + (size_t)s * 1024;
    const size_t boff = (size_t)(s * 1024) * 256 + nt * 128;
    float acc[4][4][4];
    mm_main(g_Ehi + aoff, g_Elo + aoff, XDIM, g_Hhi + boff, g_Hlo + boff, 256, 32, acc, smem);

    float* Cp = g_part + (size_t)(s * BATCH + b) * NSQ + (mt * 128) * 256 + nt * 128;
    const int lane = threadIdx.x & 31, w = threadIdx.x >> 5;
    const int wm = (w & 1) * 64, wn = (w >> 1) * 32;
#pragma unroll
    for (int mi = 0; mi < 4; mi++)
#pragma unroll
        for (int n8 = 0; n8 < 4; n8++) {
            const int r = wm + 16 * mi + (lane >> 2);
            const int cc = wn + n8 * 8 + (lane & 3) * 2;
            *(float2*)(Cp + r * 256 + cc) = make_float2(acc[mi][n8][0], acc[mi][n8][1]);
            *(float2*)(Cp + (r + 8) * 256 + cc) = make_float2(acc[mi][n8][2], acc[mi][n8][3]);
        }
}

// ---------------------------------------------------------------------------
// GEMM3: out = E + Mt @ E.  grid(64 nt, 2 mt, 8 b)
// ---------------------------------------------------------------------------
__global__ __launch_bounds__(256, 1) void k_mm3(const float* __restrict__ E,
                                                float* __restrict__ out) {
    extern __shared__ char smem[];
    const int nt = blockIdx.x, mt = blockIdx.y, b = blockIdx.z;
    const int n0 = nt * 128;
    const size_t aoff = (size_t)b * NSQ + (size_t)(mt * 128) * 256;
    const size_t boff = (size_t)b * ENSN * XDIM + n0;
    float acc[4][4][4];
    mm_main(g_Whi + aoff, g_Wlo + aoff, 256, g_Ehi + boff, g_Elo + boff, XDIM, 8, acc, smem);

    const int lane = threadIdx.x & 31, w = threadIdx.x >> 5;
    const int wm = (w & 1) * 64, wn = (w >> 1) * 32;
    const float* Ep = E + (size_t)b * ENSN * XDIM;
    float* Op = out + (size_t)b * ENSN * XDIM;
#pragma unroll
    for (int mi = 0; mi < 4; mi++)
#pragma unroll
        for (int n8 = 0; n8 < 4; n8++) {
            const int e = mt * 128 + wm + 16 * mi + (lane >> 2);
            const int x = n0 + wn + n8 * 8 + (lane & 3) * 2;
            float2 e0 = *(const float2*)(Ep + (size_t)e * XDIM + x);
            float2 e1 = *(const float2*)(Ep + (size_t)(e + 8) * XDIM + x);
            *(float2*)(Op + (size_t)e * XDIM + x) =
                make_float2(e0.x + acc[mi][n8][0], e0.y + acc[mi][n8][1]);
            *(float2*)(Op + (size_t)(e + 8) * XDIM + x) =
                make_float2(e1.x + acc[mi][n8][2], e1.y + acc[mi][n8][3]);
        }
}

// ---------------------------------------------------------------------------
// bf16 hi/lo splits (elementwise, no transposes)
// ---------------------------------------------------------------------------
__device__ __forceinline__ void split4(float4 v, __nv_bfloat162* hi, __nv_bfloat162* lo,
                                       size_t idx2) {
    __nv_bfloat16 hx = __float2bfloat16(v.x), hy = __float2bfloat16(v.y);
    __nv_bfloat16 hz = __float2bfloat16(v.z), hw = __float2bfloat16(v.w);
    hi[idx2]     = __nv_bfloat162(hx, hy);
    hi[idx2 + 1] = __nv_bfloat162(hz, hw);
    lo[idx2]     = __nv_bfloat162(__float2bfloat16(v.x - __bfloat162float(hx)),
                                  __float2bfloat16(v.y - __bfloat162float(hy)));
    lo[idx2 + 1] = __nv_bfloat162(__float2bfloat16(v.z - __bfloat162float(hz)),
                                  __float2bfloat16(v.w - __bfloat162float(hw)));
}

__global__ __launch_bounds__(256) void k_splitE(const float* __restrict__ E) {
    const size_t i = (size_t)blockIdx.x * 256 + threadIdx.x;   // over 4.19M float4
    float4 v = ((const float4*)E)[i];
    split4(v, (__nv_bfloat162*)g_Ehi, (__nv_bfloat162*)g_Elo, 2 * i);
}

__global__ __launch_bounds__(256) void k_splitH(const float* __restrict__ H) {
    const size_t i = (size_t)blockIdx.x * 256 + threadIdx.x;   // over 524288 float4
    float4 v = ((const float4*)H)[i];
    split4(v, (__nv_bfloat162*)g_Hhi, (__nv_bfloat162*)g_Hlo, 2 * i);
}

// ---------------------------------------------------------------------------
// split-K reduce
// ---------------------------------------------------------------------------
__global__ __launch_bounds__(256) void k_reduce() {
    const int i = blockIdx.x * 256 + threadIdx.x;
    const float4* P = (const float4*)g_part;
    float4 s = P[i];
#pragma unroll
    for (int p = 1; p < SPLITS; p++) {
        float4 v = P[(size_t)p * (BATCH * NSQ / 4) + i];
        s.x += v.x; s.y += v.y; s.z += v.z; s.w += v.w;
    }
    ((float4*)g_G)[i] = s;
}

__global__ __launch_bounds__(256) void k_colmean() {
    const int b = blockIdx.y;
    const int j = blockIdx.x * 32 + (threadIdx.x & 31);
    const int er = threadIdx.x >> 5;
    const float* G = g_G + b * NSQ;
    float s = 0.0f;
    for (int e = er; e < ENSN; e += 8) s += G[e * 256 + j];
    __shared__ float red[8][32];
    red[er][threadIdx.x & 31] = s;
    __syncthreads();
    if (er == 0) {
        float t = 0.0f;
#pragma unroll
        for (int r = 0; r < 8; r++) t += red[r][threadIdx.x & 31];
        g_mu[b * 256 + j] = t * (1.0f / 256.0f);
    }
}

__global__ __launch_bounds__(256) void k_centerT(const float* __restrict__ ymean,
                                                 const float* __restrict__ ystd,
                                                 const float* __restrict__ noise) {
    const int b = blockIdx.z, j0 = blockIdx.y * 32, e0 = blockIdx.x * 32;
    float* G = g_G + b * NSQ;
    float* Z = g_Z + b * NSQ;
    const float* nz = noise + b * NSQ;
    __shared__ float T[32][33];
    const int tx = threadIdx.x & 31, ty = threadIdx.x >> 5;
    const float mu = g_mu[b * 256 + j0 + tx];
#pragma unroll
    for (int r = 0; r < 4; r++) {
        const int e = e0 + ty + r * 8;
        float gc = G[e * 256 + j0 + tx] - mu;
        G[e * 256 + j0 + tx] = gc;
        T[ty + r * 8][tx] = gc;
    }
    __syncthreads();
#pragma unroll
    for (int r = 0; r < 4; r++) {
        const int j = j0 + ty + r * 8;
        const float ym = ymean[j];
        const float sd = ystd[j];
        Z[j * 256 + e0 + tx] = ym - T[tx][ty + r * 8] + nz[j * 256 + e0 + tx] * sd * sd;
    }
}

__global__ __launch_bounds__(256) void k_cyy(const float* __restrict__ ystd) {
    const int b = blockIdx.y;
    const int u0 = (blockIdx.x >> 2) * 64, v0 = (blockIdx.x & 3) * 64;
    const float* G = g_G + b * NSQ;
    float* A = g_A + b * NSQ;
    __shared__ float Us[16][64];
    __shared__ float Vs[16][64];
    const int tx = threadIdx.x & 15, ty = threadIdx.x >> 4;
    const int lk = threadIdx.x >> 4, lc = (threadIdx.x & 15) * 4;
    float acc[4][4];
#pragma unroll
    for (int i = 0; i < 4; i++)
#pragma unroll
        for (int j = 0; j < 4; j++) acc[i][j] = 0.0f;

    for (int ee = 0; ee < 256; ee += 16) {
        *(float4*)&Us[lk][lc] = *(const float4*)&G[(ee + lk) * 256 + u0 + lc];
        *(float4*)&Vs[lk][lc] = *(const float4*)&G[(ee + lk) * 256 + v0 + lc];
        __syncthreads();
#pragma unroll
        for (int k = 0; k < 16; k++) {
            float4 u = *(float4*)&Us[k][ty * 4];
            float4 v = *(float4*)&Vs[k][tx * 4];
            float ua[4] = {u.x, u.y, u.z, u.w};
            float va[4] = {v.x, v.y, v.z, v.w};
#pragma unroll
            for (int i = 0; i < 4; i++)
#pragma unroll
                for (int j = 0; j < 4; j++) acc[i][j] = fmaf(ua[i], va[j], acc[i][j]);
        }
        __syncthreads();
    }
#pragma unroll
    for (int i = 0; i < 4; i++)
#pragma unroll
        for (int j = 0; j < 4; j++) {
            const int u = u0 + ty * 4 + i, v = v0 + tx * 4 + j;
            float val = acc[i][j] * (1.0f / 256.0f);
            if (u == v) { float sd = ystd[u]; val += sd * sd; }
            A[u * 256 + v] = val;
        }
}

__global__ __launch_bounds__(256) void k_chol() {
    const int b = blockIdx.x;
    float* a = g_A + b * NSQ;
    __shared__ float P[256][33];
    const int tid = threadIdx.x;

    for (int kb = 0; kb < 8; kb++) {
        const int j0 = kb * 32;
        if (tid >= j0) {
#pragma unroll
            for (int c = 0; c < 32; c++) P[tid][c] = a[tid * 256 + j0 + c];
        }
        __syncthreads();
        for (int k = 0; k < 32; k++) {
            const int gk = j0 + k;
            const float piv = P[gk][k];
            __syncthreads();
            const float d = sqrtf(piv);
            const float rd = 1.0f / d;
            if (tid == gk) P[tid][k] = d;
            else if (tid > gk) P[tid][k] *= rd;
            __syncthreads();
            if (tid > gk) {
                const float lrk = P[tid][k];
#pragma unroll
                for (int c = k + 1; c < 32; c++) P[tid][c] -= lrk * P[j0 + c][k];
            }
            __syncthreads();
        }
        if (tid >= j0) {
#pragma unroll
            for (int c = 0; c < 32; c++) a[tid * 256 + j0 + c] = P[tid][c];
        }
        __syncthreads();
        const int rem = 224 - j0;
        if (rem > 0) {
            for (int idx = tid; idx < rem * rem; idx += 256) {
                const int r = j0 + 32 + idx / rem;
                const int c = j0 + 32 + (idx - (idx / rem) * rem);
                float acc = a[r * 256 + c];
#pragma unroll
                for (int k = 0; k < 32; k++) acc -= P[r][k] * P[c][k];
                a[r * 256 + c] = acc;
            }
        }
        __syncthreads();
    }
}

__global__ __launch_bounds__(256) void k_trisolve() {
    const int b = blockIdx.y, grp = blockIdx.x;
    const float* L = g_A + b * NSQ;
    float* Z = g_Z + b * NSQ;
    const int e0 = grp * 64;

    __shared__ float D[32][33];
    __shared__ float X[32][64];
    __shared__ float Ls[224][33];
    const int tid = threadIdx.x;

    for (int p = 0; p < 8; p++) {
        const int j0 = p * 32;
        {
            const int r = tid >> 3, cb = (tid & 7) * 4;
            float4 v = *(const float4*)&L[(j0 + r) * 256 + j0 + cb];
            D[r][cb] = v.x; D[r][cb + 1] = v.y; D[r][cb + 2] = v.z; D[r][cb + 3] = v.w;
        }
        const int rem = 224 - j0;
        for (int idx = tid; idx < rem * 32; idx += 256) {
            const int r = idx >> 5, c = idx & 31;
            Ls[r][c] = L[(j0 + 32 + r) * 256 + j0 + c];
        }
        __syncthreads();
        if (tid < 64) {
            const int c = e0 + tid;
            for (int k = 0; k < 32; k++) {
                float v = Z[(j0 + k) * 256 + c];
                for (int i = 0; i < k; i++) v -= D[k][i] * X[i][tid];
                v /= D[k][k];
                X[k][tid] = v;
                Z[(j0 + k) * 256 + c] = v;
            }
        }
        __syncthreads();
        for (int idx = tid; idx < rem * 64; idx += 256) {
            const int rr = idx >> 6, cc = idx & 63;
            float v = Z[(j0 + 32 + rr) * 256 + e0 + cc];
#pragma unroll
            for (int k = 0; k < 32; k++) v -= Ls[rr][k] * X[k][cc];
            Z[(j0 + 32 + rr) * 256 + e0 + cc] = v;
        }
        __syncthreads();
    }

    for (int p = 7; p >= 0; p--) {
        const int j0 = p * 32;
        {
            const int r = tid >> 3, cb = (tid & 7) * 4;
            float4 v = *(const float4*)&L[(j0 + r) * 256 + j0 + cb];
            D[r][cb] = v.x; D[r][cb + 1] = v.y; D[r][cb + 2] = v.z; D[r][cb + 3] = v.w;
        }
        for (int idx = tid; idx < j0 * 32; idx += 256) {
            const int r = idx >> 5, k = idx & 31;
            Ls[r][k] = L[(j0 + k) * 256 + r];
        }
        __syncthreads();
        if (tid < 64) {
            const int c = e0 + tid;
            for (int k = 31; k >= 0; k--) {
                float v = Z[(j0 + k) * 256 + c];
                for (int i = k + 1; i < 32; i++) v -= D[i][k] * X[i][tid];
                v /= D[k][k];
                X[k][tid] = v;
                Z[(j0 + k) * 256 + c] = v;
            }
        }
        __syncthreads();
        for (int idx = tid; idx < j0 * 64; idx += 256) {
            const int rr = idx >> 6, cc = idx & 63;
            float v = Z[rr * 256 + e0 + cc];
#pragma unroll
            for (int k = 0; k < 32; k++) v -= Ls[rr][k] * X[k][cc];
            Z[rr * 256 + e0 + cc] = v;
        }
        __syncthreads();
    }
}

// Mt[e][f] = (1/ens) sum_j Z[j][e] * Gc[f][j]  -> bf16 hi/lo
__global__ __launch_bounds__(256) void k_wp() {
    const int b = blockIdx.y;
    const int e0 = (blockIdx.x >> 2) * 64, f0 = (blockIdx.x & 3) * 64;
    const float* G = g_G + b * NSQ;
    const float* Z = g_Z + b * NSQ;
    __shared__ float sZ[16][64];
    __shared__ float sG[16][64];
    const int tx = threadIdx.x & 15, ty = threadIdx.x >> 4;
    const int lk = threadIdx.x >> 4, lc = (threadIdx.x & 15) * 4;
    const int gn = threadIdx.x >> 2, gk = (threadIdx.x & 3) * 4;
    float acc[4][4];
#pragma unroll
    for (int i = 0; i < 4; i++)
#pragma unroll
        for (int j = 0; j < 4; j++) acc[i][j] = 0.0f;

    for (int jj = 0; jj < 256; jj += 16) {
        *(float4*)&sZ[lk][lc] = *(const float4*)&Z[(jj + lk) * 256 + e0 + lc];
        float4 gv = *(const float4*)&G[(f0 + gn) * 256 + jj + gk];
        sG[gk + 0][gn] = gv.x; sG[gk + 1][gn] = gv.y;
        sG[gk + 2][gn] = gv.z; sG[gk + 3][gn] = gv.w;
        __syncthreads();
#pragma unroll
        for (int k = 0; k < 16; k++) {
            float4 zv = *(float4*)&sZ[k][ty * 4];
            float4 gg = *(float4*)&sG[k][tx * 4];
            float za[4] = {zv.x, zv.y, zv.z, zv.w};
            float ga[4] = {gg.x, gg.y, gg.z, gg.w};
#pragma unroll
            for (int i = 0; i < 4; i++)
#pragma unroll
                for (int j = 0; j < 4; j++) acc[i][j] = fmaf(za[i], ga[j], acc[i][j]);
        }
        __syncthreads();
    }
#pragma unroll
    for (int i = 0; i < 4; i++)
#pragma unroll
        for (int j = 0; j < 4; j++) {
            const int e = e0 + ty * 4 + i, f = f0 + tx * 4 + j;
            float val = acc[i][j] * (1.0f / 256.0f);
            __nv_bfloat16 h = __float2bfloat16(val);
            g_Whi[b * NSQ + e * 256 + f] = h;
            g_Wlo[b * NSQ + e * 256 + f] = __float2bfloat16(val - __bfloat162float(h));
        }
}

// ---------------------------------------------------------------------------
extern "C" void kernel_launch(void* const* d_in, const int* in_sizes, int n_in,
                              void* d_out, int out_size) {
    const float* E     = (const float*)d_in[0];
    const float* H     = (const float*)d_in[1];
    const float* ymean = (const float*)d_in[2];
    const float* ystd  = (const float*)d_in[3];
    const float* noise = (const float*)d_in[4];
    float* out = (float*)d_out;

    cudaFuncSetAttribute(k_mm1, cudaFuncAttributeMaxDynamicSharedMemorySize, SMEMSZ);
    cudaFuncSetAttribute(k_mm3, cudaFuncAttributeMaxDynamicSharedMemorySize, SMEMSZ);

    k_splitH<<<2048, 256>>>(H);
    k_splitE<<<16384, 256>>>(E);
    k_mm1<<<dim3(4, SPLITS, BATCH), 256, SMEMSZ>>>();
    k_reduce<<<(BATCH * NSQ / 4) / 256, 256>>>();
    k_colmean<<<dim3(8, BATCH), 256>>>();
    k_centerT<<<dim3(8, 8, BATCH), 256>>>(ymean, ystd, noise);
    k_cyy<<<dim3(16, BATCH), 256>>>(ystd);
    k_chol<<<BATCH, 256>>>();
    k_trisolve<<<dim3(4, BATCH), 256>>>();
    k_wp<<<dim3(16, BATCH), 256>>>();
    k_mm3<<<dim3(64, 2, BATCH), 256, SMEMSZ>>>(E, out);
}

// round 5
// speedup vs baseline: 1.6267x; 1.1343x over previous
#include <cuda_runtime.h>
#include <cuda_fp16.h>
#include <cstdint>

// EnsKF step. Legacy tensor path (compute_103 portable ISA), fp16 3-term splits:
//   G  = E @ H          (mma.m16n8k16.f16, hh+hl+lh, split-K)
//   Gc = G - colmean;  A = Gc^T Gc/ens + diag(std^2);  L = chol(A)
//   Dinv = inverses of L's 32x32 diagonal blocks
//   Z  = A^{-1} innov   (blocked trisolve, Z in smem, Dinv matmuls)
//   Mt[e][f] = (1/ens) sum_j Z[j][e] Gc[f][j]  -> fp16 hi/lo
//   out = E + Mt @ E    (mma fp16 3-term, epilogue adds E)

#define BATCH 8
#define ENSN  256
#define XDIM  8192
#define NSQ   65536
#define SPLITS 8

__device__ __align__(256) float g_part[SPLITS * BATCH * NSQ];
__device__ __align__(256) float g_G[BATCH * NSQ];
__device__ __align__(256) float g_mu[BATCH * 256];
__device__ __align__(256) float g_A[BATCH * NSQ];
__device__ __align__(256) float g_Z[BATCH * NSQ];
__device__ __align__(256) float g_Dinv[BATCH * 8 * 32 * 32];
__device__ __align__(256) __half g_Ehi[BATCH * ENSN * XDIM];
__device__ __align__(256) __half g_Elo[BATCH * ENSN * XDIM];
__device__ __align__(256) __half g_Hhi[XDIM * 256];
__device__ __align__(256) __half g_Hlo[XDIM * 256];
__device__ __align__(256) __half g_Whi[BATCH * NSQ];
__device__ __align__(256) __half g_Wlo[BATCH * NSQ];

// ---------------- smem layout (bytes) for GEMMs ----------------
#define SM_A(buf, hl) ((buf) * 20480 + (hl) * 10240)
#define SM_B(buf, hl) (40960 + (buf) * 17408 + (hl) * 8704)
#define SMEMSZ (40960 + 34816)

// ---------------- low-level helpers ----------------
__device__ __forceinline__ uint32_t smem_u32(const void* p) {
    uint32_t a;
    asm("{ .reg .u64 t; cvta.to.shared.u64 t, %1; cvt.u32.u64 %0, t; }" : "=r"(a) : "l"(p));
    return a;
}
__device__ __forceinline__ void cpa16(uint32_t dst, const void* src) {
    asm volatile("cp.async.cg.shared.global [%0], [%1], 16;" :: "r"(dst), "l"(src));
}
__device__ __forceinline__ void ldsm4(uint32_t* r, uint32_t a) {
    asm volatile("ldmatrix.sync.aligned.m8n8.x4.shared.b16 {%0,%1,%2,%3}, [%4];"
                 : "=r"(r[0]), "=r"(r[1]), "=r"(r[2]), "=r"(r[3]) : "r"(a));
}
__device__ __forceinline__ void ldsm4t(uint32_t* r, uint32_t a) {
    asm volatile("ldmatrix.sync.aligned.m8n8.x4.trans.shared.b16 {%0,%1,%2,%3}, [%4];"
                 : "=r"(r[0]), "=r"(r[1]), "=r"(r[2]), "=r"(r[3]) : "r"(a));
}
__device__ __forceinline__ void mma16816(float* c, const uint32_t* a, const uint32_t* b) {
    asm volatile("mma.sync.aligned.m16n8k16.row.col.f32.f16.f16.f32 "
                 "{%0,%1,%2,%3},{%4,%5,%6,%7},{%8,%9},{%0,%1,%2,%3};"
                 : "+f"(c[0]), "+f"(c[1]), "+f"(c[2]), "+f"(c[3])
                 : "r"(a[0]), "r"(a[1]), "r"(a[2]), "r"(a[3]), "r"(b[0]), "r"(b[1]));
}

// ---------------- tile producers ----------------
__device__ __forceinline__ void issue_tiles(
    uint32_t sb, int buf,
    const __half* __restrict__ Ahi, const __half* __restrict__ Alo, size_t lda,
    const __half* __restrict__ Bhi, const __half* __restrict__ Blo, size_t ldb,
    int kbase, int tid)
{
#pragma unroll
    for (int half_ = 0; half_ < 2; half_++) {
        const __half* src = half_ ? Alo : Ahi;
#pragma unroll
        for (int it = 0; it < 2; it++) {
            const int i = tid + it * 256;
            const int r = i >> 2, seg = i & 3;
            cpa16(sb + SM_A(buf, half_) + r * 80 + seg * 16,
                  src + (size_t)r * lda + kbase + seg * 8);
        }
    }
#pragma unroll
    for (int half_ = 0; half_ < 2; half_++) {
        const __half* src = half_ ? Blo : Bhi;
#pragma unroll
        for (int it = 0; it < 2; it++) {
            const int i = tid + it * 256;
            const int r = i >> 4, seg = i & 15;
            cpa16(sb + SM_B(buf, half_) + r * 272 + seg * 16,
                  src + (size_t)(kbase + r) * ldb + seg * 8);
        }
    }
}

// ---------------- warp compute: one 32-K chunk, 3-term fp16 split ----------------
__device__ __forceinline__ void compute_chunk(uint32_t sb, int buf, int lane,
                                              int wm, int wn, float acc[4][4][4]) {
    const int arow = lane & 15, aoff = (lane >> 4) * 16;
    const int brow = (lane & 7) + ((lane >> 3) & 1) * 8, boff = (lane >> 4) * 16;
#pragma unroll
    for (int k16 = 0; k16 < 2; k16++) {
        uint32_t ah[4][4], al[4][4], bh[2][4], bl[2][4];
#pragma unroll
        for (int mi = 0; mi < 4; mi++)
            ldsm4(ah[mi], sb + SM_A(buf, 0) + (wm + 16 * mi + arow) * 80 + k16 * 32 + aoff);
#pragma unroll
        for (int nj = 0; nj < 2; nj++)
            ldsm4t(bh[nj], sb + SM_B(buf, 0) + (k16 * 16 + brow) * 272 + (wn + nj * 16) * 2 + boff);
#pragma unroll
        for (int mi = 0; mi < 4; mi++)
#pragma unroll
            for (int n8 = 0; n8 < 4; n8++)
                mma16816(acc[mi][n8], ah[mi], &bh[n8 >> 1][(n8 & 1) * 2]);
#pragma unroll
        for (int nj = 0; nj < 2; nj++)
            ldsm4t(bl[nj], sb + SM_B(buf, 1) + (k16 * 16 + brow) * 272 + (wn + nj * 16) * 2 + boff);
#pragma unroll
        for (int mi = 0; mi < 4; mi++)
#pragma unroll
            for (int n8 = 0; n8 < 4; n8++)
                mma16816(acc[mi][n8], ah[mi], &bl[n8 >> 1][(n8 & 1) * 2]);
#pragma unroll
        for (int mi = 0; mi < 4; mi++)
            ldsm4(al[mi], sb + SM_A(buf, 1) + (wm + 16 * mi + arow) * 80 + k16 * 32 + aoff);
#pragma unroll
        for (int mi = 0; mi < 4; mi++)
#pragma unroll
            for (int n8 = 0; n8 < 4; n8++)
                mma16816(acc[mi][n8], al[mi], &bh[n8 >> 1][(n8 & 1) * 2]);
    }
}

// ---------------- main accumulate driver (128m x 128n CTA) ----------------
__device__ __forceinline__ void mm_main(
    const __half* Ahi, const __half* Alo, size_t lda,
    const __half* Bhi, const __half* Blo, size_t ldb,
    int nch, float acc[4][4][4], char* smem)
{
    const uint32_t sb = smem_u32(smem);
    const int tid = threadIdx.x, lane = tid & 31, w = tid >> 5;
    const int wm = (w & 1) * 64, wn = (w >> 1) * 32;
#pragma unroll
    for (int i = 0; i < 4; i++)
#pragma unroll
        for (int j = 0; j < 4; j++)
#pragma unroll
            for (int q = 0; q < 4; q++) acc[i][j][q] = 0.0f;

    issue_tiles(sb, 0, Ahi, Alo, lda, Bhi, Blo, ldb, 0, tid);
    asm volatile("cp.async.commit_group;" ::: "memory");
    issue_tiles(sb, 1, Ahi, Alo, lda, Bhi, Blo, ldb, 32, tid);
    asm volatile("cp.async.commit_group;" ::: "memory");

    for (int c = 0; c < nch; c++) {
        asm volatile("cp.async.wait_group 1;" ::: "memory");
        __syncthreads();
        compute_chunk(sb, c & 1, lane, wm, wn, acc);
        __syncthreads();
        if (c + 2 < nch)
            issue_tiles(sb, c & 1, Ahi, Alo, lda, Bhi, Blo, ldb, (c + 2) * 32, tid);
        asm volatile("cp.async.commit_group;" ::: "memory");
    }
}

// ---------------------------------------------------------------------------
// GEMM1: split-K partials of G = E @ H.  grid(4 = mt*2+nt, 8 splits, 8 b)
// ---------------------------------------------------------------------------
__global__ __launch_bounds__(256, 1) void k_mm1() {
    extern __shared__ char smem[];
    const int mt = blockIdx.x >> 1, nt = blockIdx.x & 1;
    const int s = blockIdx.y, b = blockIdx.z;
    const size_t aoff = ((size_t)b * ENSN + mt * 128) * XDIM + (size_t)s * 1024;
    const size_t boff = (size_t)(s * 1024) * 256 + nt * 128;
    float acc[4][4][4];
    mm_main(g_Ehi + aoff, g_Elo + aoff, XDIM, g_Hhi + boff, g_Hlo + boff, 256, 32, acc, smem);

    float* Cp = g_part + (size_t)(s * BATCH + b) * NSQ + (mt * 128) * 256 + nt * 128;
    const int lane = threadIdx.x & 31, w = threadIdx.x >> 5;
    const int wm = (w & 1) * 64, wn = (w >> 1) * 32;
#pragma unroll
    for (int mi = 0; mi < 4; mi++)
#pragma unroll
        for (int n8 = 0; n8 < 4; n8++) {
            const int r = wm + 16 * mi + (lane >> 2);
            const int cc = wn + n8 * 8 + (lane & 3) * 2;
            *(float2*)(Cp + r * 256 + cc) = make_float2(acc[mi][n8][0], acc[mi][n8][1]);
            *(float2*)(Cp + (r + 8) * 256 + cc) = make_float2(acc[mi][n8][2], acc[mi][n8][3]);
        }
}

// ---------------------------------------------------------------------------
// GEMM3: out = E + Mt @ E.  grid(64 nt, 2 mt, 8 b)
// ---------------------------------------------------------------------------
__global__ __launch_bounds__(256, 1) void k_mm3(const float* __restrict__ E,
                                                float* __restrict__ out) {
    extern __shared__ char smem[];
    const int nt = blockIdx.x, mt = blockIdx.y, b = blockIdx.z;
    const int n0 = nt * 128;
    const size_t aoff = (size_t)b * NSQ + (size_t)(mt * 128) * 256;
    const size_t boff = (size_t)b * ENSN * XDIM + n0;
    float acc[4][4][4];
    mm_main(g_Whi + aoff, g_Wlo + aoff, 256, g_Ehi + boff, g_Elo + boff, XDIM, 8, acc, smem);

    const int lane = threadIdx.x & 31, w = threadIdx.x >> 5;
    const int wm = (w & 1) * 64, wn = (w >> 1) * 32;
    const float* Ep = E + (size_t)b * ENSN * XDIM;
    float* Op = out + (size_t)b * ENSN * XDIM;
#pragma unroll
    for (int mi = 0; mi < 4; mi++)
#pragma unroll
        for (int n8 = 0; n8 < 4; n8++) {
            const int e = mt * 128 + wm + 16 * mi + (lane >> 2);
            const int x = n0 + wn + n8 * 8 + (lane & 3) * 2;
            float2 e0 = *(const float2*)(Ep + (size_t)e * XDIM + x);
            float2 e1 = *(const float2*)(Ep + (size_t)(e + 8) * XDIM + x);
            *(float2*)(Op + (size_t)e * XDIM + x) =
                make_float2(e0.x + acc[mi][n8][0], e0.y + acc[mi][n8][1]);
            *(float2*)(Op + (size_t)(e + 8) * XDIM + x) =
                make_float2(e1.x + acc[mi][n8][2], e1.y + acc[mi][n8][3]);
        }
}

// ---------------------------------------------------------------------------
// fp16 hi/lo splits (elementwise)
// ---------------------------------------------------------------------------
__device__ __forceinline__ void split4h(float4 v, __half2* hi, __half2* lo, size_t idx2) {
    __half hx = __float2half_rn(v.x), hy = __float2half_rn(v.y);
    __half hz = __float2half_rn(v.z), hw = __float2half_rn(v.w);
    hi[idx2]     = __halves2half2(hx, hy);
    hi[idx2 + 1] = __halves2half2(hz, hw);
    lo[idx2]     = __halves2half2(__float2half_rn(v.x - __half2float(hx)),
                                  __float2half_rn(v.y - __half2float(hy)));
    lo[idx2 + 1] = __halves2half2(__float2half_rn(v.z - __half2float(hz)),
                                  __float2half_rn(v.w - __half2float(hw)));
}

__global__ __launch_bounds__(256) void k_splitE(const float* __restrict__ E) {
    const size_t i = (size_t)blockIdx.x * 256 + threadIdx.x;
    float4 v = ((const float4*)E)[i];
    split4h(v, (__half2*)g_Ehi, (__half2*)g_Elo, 2 * i);
}

__global__ __launch_bounds__(256) void k_splitH(const float* __restrict__ H) {
    const size_t i = (size_t)blockIdx.x * 256 + threadIdx.x;
    float4 v = ((const float4*)H)[i];
    split4h(v, (__half2*)g_Hhi, (__half2*)g_Hlo, 2 * i);
}

// ---------------------------------------------------------------------------
__global__ __launch_bounds__(256) void k_reduce() {
    const int i = blockIdx.x * 256 + threadIdx.x;
    const float4* P = (const float4*)g_part;
    float4 s = P[i];
#pragma unroll
    for (int p = 1; p < SPLITS; p++) {
        float4 v = P[(size_t)p * (BATCH * NSQ / 4) + i];
        s.x += v.x; s.y += v.y; s.z += v.z; s.w += v.w;
    }
    ((float4*)g_G)[i] = s;
}

__global__ __launch_bounds__(256) void k_colmean() {
    const int b = blockIdx.y;
    const int j = blockIdx.x * 32 + (threadIdx.x & 31);
    const int er = threadIdx.x >> 5;
    const float* G = g_G + b * NSQ;
    float s = 0.0f;
    for (int e = er; e < ENSN; e += 8) s += G[e * 256 + j];
    __shared__ float red[8][32];
    red[er][threadIdx.x & 31] = s;
    __syncthreads();
    if (er == 0) {
        float t = 0.0f;
#pragma unroll
        for (int r = 0; r < 8; r++) t += red[r][threadIdx.x & 31];
        g_mu[b * 256 + j] = t * (1.0f / 256.0f);
    }
}

__global__ __launch_bounds__(256) void k_centerT(const float* __restrict__ ymean,
                                                 const float* __restrict__ ystd,
                                                 const float* __restrict__ noise) {
    const int b = blockIdx.z, j0 = blockIdx.y * 32, e0 = blockIdx.x * 32;
    float* G = g_G + b * NSQ;
    float* Z = g_Z + b * NSQ;
    const float* nz = noise + b * NSQ;
    __shared__ float T[32][33];
    const int tx = threadIdx.x & 31, ty = threadIdx.x >> 5;
    const float mu = g_mu[b * 256 + j0 + tx];
#pragma unroll
    for (int r = 0; r < 4; r++) {
        const int e = e0 + ty + r * 8;
        float gc = G[e * 256 + j0 + tx] - mu;
        G[e * 256 + j0 + tx] = gc;
        T[ty + r * 8][tx] = gc;
    }
    __syncthreads();
#pragma unroll
    for (int r = 0; r < 4; r++) {
        const int j = j0 + ty + r * 8;
        const float ym = ymean[j];
        const float sd = ystd[j];
        Z[j * 256 + e0 + tx] = ym - T[tx][ty + r * 8] + nz[j * 256 + e0 + tx] * sd * sd;
    }
}

__global__ __launch_bounds__(256) void k_cyy(const float* __restrict__ ystd) {
    const int b = blockIdx.y;
    const int u0 = (blockIdx.x >> 2) * 64, v0 = (blockIdx.x & 3) * 64;
    const float* G = g_G + b * NSQ;
    float* A = g_A + b * NSQ;
    __shared__ float Us[16][64];
    __shared__ float Vs[16][64];
    const int tx = threadIdx.x & 15, ty = threadIdx.x >> 4;
    const int lk = threadIdx.x >> 4, lc = (threadIdx.x & 15) * 4;
    float acc[4][4];
#pragma unroll
    for (int i = 0; i < 4; i++)
#pragma unroll
        for (int j = 0; j < 4; j++) acc[i][j] = 0.0f;

    for (int ee = 0; ee < 256; ee += 16) {
        *(float4*)&Us[lk][lc] = *(const float4*)&G[(ee + lk) * 256 + u0 + lc];
        *(float4*)&Vs[lk][lc] = *(const float4*)&G[(ee + lk) * 256 + v0 + lc];
        __syncthreads();
#pragma unroll
        for (int k = 0; k < 16; k++) {
            float4 u = *(float4*)&Us[k][ty * 4];
            float4 v = *(float4*)&Vs[k][tx * 4];
            float ua[4] = {u.x, u.y, u.z, u.w};
            float va[4] = {v.x, v.y, v.z, v.w};
#pragma unroll
            for (int i = 0; i < 4; i++)
#pragma unroll
                for (int j = 0; j < 4; j++) acc[i][j] = fmaf(ua[i], va[j], acc[i][j]);
        }
        __syncthreads();
    }
#pragma unroll
    for (int i = 0; i < 4; i++)
#pragma unroll
        for (int j = 0; j < 4; j++) {
            const int u = u0 + ty * 4 + i, v = v0 + tx * 4 + j;
            float val = acc[i][j] * (1.0f / 256.0f);
            if (u == v) { float sd = ystd[u]; val += sd * sd; }
            A[u * 256 + v] = val;
        }
}

// ---------------------------------------------------------------------------
// Blocked Cholesky, 2 syncs per pivot (diag kept in sD)
// ---------------------------------------------------------------------------
__global__ __launch_bounds__(256) void k_chol() {
    const int b = blockIdx.x;
    float* a = g_A + b * NSQ;
    __shared__ float P[256][33];
    __shared__ float sD[32];
    const int tid = threadIdx.x;

    for (int kb = 0; kb < 8; kb++) {
        const int j0 = kb * 32;
        if (tid >= j0) {
#pragma unroll
            for (int c = 0; c < 32; c++) P[tid][c] = a[tid * 256 + j0 + c];
        }
        __syncthreads();
        for (int k = 0; k < 32; k++) {
            const int gk = j0 + k;
            const float piv = P[gk][k];
            const float d = sqrtf(piv);
            const float rd = 1.0f / d;
            if (tid == gk) sD[k] = d;
            if (tid > gk) P[tid][k] *= rd;
            __syncthreads();
            if (tid > gk) {
                const float lrk = P[tid][k];
#pragma unroll
                for (int c = k + 1; c < 32; c++) P[tid][c] -= lrk * P[j0 + c][k];
            }
            __syncthreads();
        }
        if (tid >= j0) {
#pragma unroll
            for (int c = 0; c < 32; c++) {
                float val = P[tid][c];
                if (tid - j0 == c) val = sD[c];
                a[tid * 256 + j0 + c] = val;
            }
        }
        __syncthreads();
        const int rem = 224 - j0;
        if (rem > 0) {
            for (int idx = tid; idx < rem * rem; idx += 256) {
                const int r = j0 + 32 + idx / rem;
                const int c = j0 + 32 + (idx - (idx / rem) * rem);
                float acc = a[r * 256 + c];
#pragma unroll
                for (int k = 0; k < 32; k++) acc -= P[r][k] * P[c][k];
                a[r * 256 + c] = acc;
            }
        }
        __syncthreads();
    }
}

// ---------------------------------------------------------------------------
// Invert the 8 lower-triangular 32x32 diagonal blocks of L. grid(64), 32 thr
// ---------------------------------------------------------------------------
__global__ void k_invdiag() {
    const int p = blockIdx.x & 7, b = blockIdx.x >> 3, j0 = p * 32;
    const float* a = g_A + b * NSQ;
    __shared__ float Ld[32][33];
    __shared__ float Xc[32][33];
    const int lane = threadIdx.x;
    for (int i = 0; i < 32; i++) Ld[i][lane] = a[(j0 + i) * 256 + j0 + lane];
    __syncwarp();
    for (int i = 0; i < 32; i++) {
        float s = (i == lane) ? 1.0f : 0.0f;
        for (int k = lane; k < i; k++) s -= Ld[i][k] * Xc[k][lane];
        Xc[i][lane] = (i >= lane) ? s / Ld[i][i] : 0.0f;
    }
    __syncwarp();
    for (int i = 0; i < 32; i++)
        g_Dinv[(b * 8 + p) * 1024 + i * 32 + lane] = Xc[i][lane];
}

// ---------------------------------------------------------------------------
// Trisolve with smem-resident Z and Dinv matmuls. grid(4 grp, 8 b), 256 thr
// smem: Zs 256x65 | Dv 256x33 | Lp 224x33  = 129,920 B
// ---------------------------------------------------------------------------
#define TS_SMEM 129920
__global__ __launch_bounds__(256) void k_trisolve2() {
    extern __shared__ float sm[];
    float (*Zs)[65] = (float(*)[65])sm;
    float (*Dv)[33] = (float(*)[33])(sm + 256 * 65);
    float (*Lp)[33] = (float(*)[33])(sm + 256 * 65 + 256 * 33);
    const int b = blockIdx.y, e0 = blockIdx.x * 64;
    const float* L = g_A + b * NSQ;
    float* Z = g_Z + b * NSQ;
    const int tid = threadIdx.x, c = tid & 63, rg = tid >> 6;

    for (int idx = tid; idx < 256 * 64; idx += 256)
        Zs[idx >> 6][idx & 63] = Z[(idx >> 6) * 256 + e0 + (idx & 63)];
    for (int idx = tid; idx < 8 * 32 * 32; idx += 256) {
        const int p = idx >> 10, i = (idx >> 5) & 31, k = idx & 31;
        Dv[p * 32 + i][k] = g_Dinv[b * 8192 + idx];
        (void)p; (void)i; (void)k;
    }
    __syncthreads();

    // forward: L y = innov
    for (int p = 0; p < 8; p++) {
        const int j0 = p * 32, rem = 224 - j0;
        float w[8];
#pragma unroll
        for (int q = 0; q < 8; q++) {
            const int r = rg * 8 + q;
            float s = 0.0f;
#pragma unroll
            for (int k = 0; k < 32; k++) s = fmaf(Dv[p * 32 + r][k], Zs[j0 + k][c], s);
            w[q] = s;
        }
        for (int idx = tid; idx < rem * 32; idx += 256)
            Lp[idx >> 5][idx & 31] = L[(j0 + 32 + (idx >> 5)) * 256 + j0 + (idx & 31)];
        __syncthreads();
#pragma unroll
        for (int q = 0; q < 8; q++) Zs[j0 + rg * 8 + q][c] = w[q];
        __syncthreads();
        for (int rr = rg; rr < rem; rr += 4) {
            float acc = Zs[j0 + 32 + rr][c];
#pragma unroll
            for (int k = 0; k < 32; k++) acc = fmaf(-Lp[rr][k], Zs[j0 + k][c], acc);
            Zs[j0 + 32 + rr][c] = acc;
        }
        __syncthreads();
    }

    // backward: L^T z = y
    for (int p = 7; p >= 0; p--) {
        const int j0 = p * 32;
        float w[8];
#pragma unroll
        for (int q = 0; q < 8; q++) {
            const int k = rg * 8 + q;
            float s = 0.0f;
#pragma unroll
            for (int i = 0; i < 32; i++) s = fmaf(Dv[p * 32 + i][k], Zs[j0 + i][c], s);
            w[q] = s;
        }
        for (int idx = tid; idx < j0 * 32; idx += 256)
            Lp[idx >> 5][idx & 31] = L[(j0 + (idx & 31)) * 256 + (idx >> 5)];
        __syncthreads();
#pragma unroll
        for (int q = 0; q < 8; q++) Zs[j0 + rg * 8 + q][c] = w[q];
        __syncthreads();
        for (int t = rg; t < j0; t += 4) {
            float acc = Zs[t][c];
#pragma unroll
            for (int k = 0; k < 32; k++) acc = fmaf(-Lp[t][k], Zs[j0 + k][c], acc);
            Zs[t][c] = acc;
        }
        __syncthreads();
    }

    for (int idx = tid; idx < 256 * 64; idx += 256)
        Z[(idx >> 6) * 256 + e0 + (idx & 63)] = Zs[idx >> 6][idx & 63];
}

// Mt[e][f] = (1/ens) sum_j Z[j][e] * Gc[f][j]  -> fp16 hi/lo
__global__ __launch_bounds__(256) void k_wp() {
    const int b = blockIdx.y;
    const int e0 = (blockIdx.x >> 2) * 64, f0 = (blockIdx.x & 3) * 64;
    const float* G = g_G + b * NSQ;
    const float* Z = g_Z + b * NSQ;
    __shared__ float sZ[16][64];
    __shared__ float sG[16][64];
    const int tx = threadIdx.x & 15, ty = threadIdx.x >> 4;
    const int lk = threadIdx.x >> 4, lc = (threadIdx.x & 15) * 4;
    const int gn = threadIdx.x >> 2, gk = (threadIdx.x & 3) * 4;
    float acc[4][4];
#pragma unroll
    for (int i = 0; i < 4; i++)
#pragma unroll
        for (int j = 0; j < 4; j++) acc[i][j] = 0.0f;

    for (int jj = 0; jj < 256; jj += 16) {
        *(float4*)&sZ[lk][lc] = *(const float4*)&Z[(jj + lk) * 256 + e0 + lc];
        float4 gv = *(const float4*)&G[(f0 + gn) * 256 + jj + gk];
        sG[gk + 0][gn] = gv.x; sG[gk + 1][gn] = gv.y;
        sG[gk + 2][gn] = gv.z; sG[gk + 3][gn] = gv.w;
        __syncthreads();
#pragma unroll
        for (int k = 0; k < 16; k++) {
            float4 zv = *(float4*)&sZ[k][ty * 4];
            float4 gg = *(float4*)&sG[k][tx * 4];
            float za[4] = {zv.x, zv.y, zv.z, zv.w};
            float ga[4] = {gg.x, gg.y, gg.z, gg.w};
#pragma unroll
            for (int i = 0; i < 4; i++)
#pragma unroll
                for (int j = 0; j < 4; j++) acc[i][j] = fmaf(za[i], ga[j], acc[i][j]);
        }
        __syncthreads();
    }
#pragma unroll
    for (int i = 0; i < 4; i++)
#pragma unroll
        for (int j = 0; j < 4; j++) {
            const int e = e0 + ty * 4 + i, f = f0 + tx * 4 + j;
            float val = acc[i][j] * (1.0f / 256.0f);
            __half h = __float2half_rn(val);
            g_Whi[b * NSQ + e * 256 + f] = h;
            g_Wlo[b * NSQ + e * 256 + f] = __float2half_rn(val - __half2float(h));
        }
}

// ---------------------------------------------------------------------------
extern "C" void kernel_launch(void* const* d_in, const int* in_sizes, int n_in,
                              void* d_out, int out_size) {
    const float* E     = (const float*)d_in[0];
    const float* H     = (const float*)d_in[1];
    const float* ymean = (const float*)d_in[2];
    const float* ystd  = (const float*)d_in[3];
    const float* noise = (const float*)d_in[4];
    float* out = (float*)d_out;

    cudaFuncSetAttribute(k_mm1, cudaFuncAttributeMaxDynamicSharedMemorySize, SMEMSZ);
    cudaFuncSetAttribute(k_mm3, cudaFuncAttributeMaxDynamicSharedMemorySize, SMEMSZ);
    cudaFuncSetAttribute(k_trisolve2, cudaFuncAttributeMaxDynamicSharedMemorySize, TS_SMEM);

    k_splitH<<<2048, 256>>>(H);
    k_splitE<<<16384, 256>>>(E);
    k_mm1<<<dim3(4, SPLITS, BATCH), 256, SMEMSZ>>>();
    k_reduce<<<(BATCH * NSQ / 4) / 256, 256>>>();
    k_colmean<<<dim3(8, BATCH), 256>>>();
    k_centerT<<<dim3(8, 8, BATCH), 256>>>(ymean, ystd, noise);
    k_cyy<<<dim3(16, BATCH), 256>>>(ystd);
    k_chol<<<BATCH, 256>>>();
    k_invdiag<<<64, 32>>>();
    k_trisolve2<<<dim3(4, BATCH), 256, TS_SMEM>>>();
    k_wp<<<dim3(16, BATCH), 256>>>();
    k_mm3<<<dim3(64, 2, BATCH), 256, SMEMSZ>>>(E, out);
}